// round 11
// baseline (speedup 1.0000x reference)
#include <cuda_runtime.h>

#define K 48
#define STOPID 47
#define CHUNK 16
#define NWARP 4
#define CLAMPV 1e32f

typedef unsigned long long ull;

// ---------- packed f32x2 helpers (Blackwell sm_103a) ----------
__device__ __forceinline__ ull pack2(float x, float y) {
    ull r;
    asm("mov.b64 %0, {%1, %2};" : "=l"(r)
        : "r"(__float_as_uint(x)), "r"(__float_as_uint(y)));
    return r;
}
__device__ __forceinline__ void unpack2(ull v, float& x, float& y) {
    unsigned int a, b;
    asm("mov.b64 {%0, %1}, %2;" : "=r"(a), "=r"(b) : "l"(v));
    x = __uint_as_float(a);
    y = __uint_as_float(b);
}
__device__ __forceinline__ ull fma2(ull a, ull b, ull c) {
    ull d;
    asm("fma.rn.f32x2 %0, %1, %2, %3;" : "=l"(d) : "l"(a), "l"(b), "l"(c));
    return d;
}
__device__ __forceinline__ ull add2(ull a, ull b) {
    ull d;
    asm("add.rn.f32x2 %0, %1, %2;" : "=l"(d) : "l"(a), "l"(b));
    return d;
}
__device__ __forceinline__ void cp_async16(unsigned int s, const void* g) {
    asm volatile("cp.async.cg.shared.global [%0], [%1], 16;" :: "r"(s), "l"(g));
}

// One warp per sequence (512 warps, 1/SMSP — proven optimal geometry R5/R8).
// 48x48 matvec as 96 half-rows: lane group h in {0,1} covers j in [24h,24h+24),
// lanes l16=0..15 own rows 3*l16..3*l16+2. Per lane: 36 fma2 + 6 broadcast
// LDS.128 + 1 shfl_xor(16) per row. After the combine BOTH halves hold full
// p' -> all 32 lanes store to their group's smem copy (no divergent branch).
//
// R10: NO per-step __syncwarp. The full-mask shfl_xor each step re-converges
// the warp before the STS; the dependent LDS next step is a later same-warp
// smem op, ordered by the in-order L1tex wavefront queue. Compiler barrier
// only. Renorm (every 8th step) moved fully OFF the serial chain by
// pre-scaling ex and the mask-fallback with rcp(p0_in). Emission multiply
// hoisted before the shfl (partner lanes share rows -> identical ex).
__global__ __launch_bounds__(128, 1) void crf_fwd_kernel(
    const float* __restrict__ h_tag,   // [B, T, K]
    const float* __restrict__ mask,    // [B, T]
    const float* __restrict__ trans,   // [K, K]
    float* __restrict__ out,           // [B]
    int B, int T)
{
    __shared__ __align__(16) float emb[NWARP][2][CHUNK * K];  // emit chunks
    __shared__ __align__(16) float mkb[NWARP][2][CHUNK];      // mask chunks
    __shared__ __align__(16) float pb [NWARP][2][2][K];       // [buf][copy][K]

    const int w    = threadIdx.x >> 5;
    const int lane = threadIdx.x & 31;
    const int b    = blockIdx.x * NWARP + w;
    if (b >= B) return;

    const int l16   = lane & 15;
    const int h     = lane >> 4;
    const int row0  = 3 * l16;
    const int jbase = 24 * h;

    // E2[r][m] = ( exp(trans[row0+r][jbase+2m]), exp(trans[row0+r][jbase+2m+1]) )
    ull E2[3][12];
#pragma unroll
    for (int r = 0; r < 3; r++) {
        const float* tr = trans + (row0 + r) * K + jbase;
#pragma unroll
        for (int m = 0; m < 12; m++)
            E2[r][m] = pack2(__expf(tr[2 * m]), __expf(tr[2 * m + 1]));
    }

    const float* hb = h_tag + (size_t)b * T * K;
    const float* mb = mask + (size_t)b * T;

    // init: score = NEG except STOP=0 -> c=-1e4, p=1 normal, p_STOP clamped to
    // 1e32 (feeds only the PAD track, ~e^4000 below answer; validated R3-R9).
    float pr[3], c = -1.0e4f;
#pragma unroll
    for (int r = 0; r < 3; r++) {
        pr[r] = (row0 + r == STOPID) ? CLAMPV : 1.0f;
        pb[w][0][h][row0 + r] = pr[r];   // both copies filled (h = 0 and 1)
    }

    const int nc    = (T + CHUNK - 1) / CHUNK;
    const int nfull = T / CHUNK;

    auto prefetch = [&](int ch) {
        const int t0n = ch * CHUNK;
        const int nb  = ch & 1;
        const size_t base = (size_t)t0n * K;
        unsigned int se = (unsigned int)__cvta_generic_to_shared(&emb[w][nb][0]);
#pragma unroll
        for (int i = 0; i < 6; i++) {     // CHUNK*K*4 = 3072B = 192 x 16B
            int seg = lane + 32 * i;
            if (base + (size_t)(seg + 1) * 4 <= (size_t)T * K)
                cp_async16(se + seg * 16, hb + base + seg * 4);
        }
        unsigned int sm = (unsigned int)__cvta_generic_to_shared(&mkb[w][nb][0]);
        if (lane < 4 && t0n + (lane + 1) * 4 <= T)
            cp_async16(sm + lane * 16, mb + t0n + lane * 4);
        asm volatile("cp.async.commit_group;");
    };

    prefetch(0);

    // ---------------- main: full 16-step chunks, 8-step unrolled bodies ----
    for (int ch = 0; ch < nfull; ch++) {
        const int cb = ch & 1;
        if (ch + 1 < nc) {
            prefetch(ch + 1);
            asm volatile("cp.async.wait_group 1;");
        } else {
            asm volatile("cp.async.wait_group 0;");
        }
        __syncwarp();   // once per 8/16 steps: order chunk consumption

        for (int hf = 0; hf < 2; hf++) {
            const float* ebh = &emb[w][cb][hf * 8 * K + row0];
            const float* mkh = &mkb[w][cb][hf * 8];
#pragma unroll
            for (int s8 = 0; s8 < 8; s8++) {
                const int  rp = s8 & 1;        // read parity (hf*8 is even)
                const int  wp = rp ^ 1;
                const bool RN = (s8 == 7);     // compile-time renorm predicate

                asm volatile("" ::: "memory"); // compiler barrier (no WARPSYNC)

                // chain head: p operands (own copy, broadcast LDS.128 x6)
                const ulonglong2* pu =
                    (const ulonglong2*)(&pb[w][rp][h][jbase]);
                ulonglong2 u0 = pu[0], u1 = pu[1], u2 = pu[2];
                ulonglong2 u3 = pu[3], u4 = pu[4], u5 = pu[5];

                // ---- off-chain work (runs under the fma burst) ----
                const float* eb = ebh + s8 * K;
                float ex0 = __expf(eb[0]);
                float ex1 = __expf(eb[1]);
                float ex2 = __expf(eb[2]);
                float mk  = mkh[s8];
                bool  upd = (mk != 0.0f);

                float fb0 = pr[0], fb1 = pr[1], fb2 = pr[2]; // mask fallback
                if (RN) {
                    float p0in = pb[w][rp][h][0];
                    float rv;
                    asm("rcp.approx.f32 %0, %1;" : "=f"(rv) : "f"(p0in));
                    // renorm folded off-chain: scale ex and fallback
                    ex0 *= rv; ex1 *= rv; ex2 *= rv;
                    fb0 *= rv; fb1 *= rv; fb2 *= rv;
                    c += __logf(p0in);
                }

                // ---- 36 fma2, 12 accumulators (3-deep chains) ----
                ull ax[3][2] = {{0,0},{0,0},{0,0}};
                ull ay[3][2] = {{0,0},{0,0},{0,0}};
                const ulonglong2 uu[6] = {u0, u1, u2, u3, u4, u5};
#pragma unroll
                for (int i = 0; i < 6; i++) {
                    const int par = i & 1;
#pragma unroll
                    for (int r = 0; r < 3; r++) {
                        ax[r][par] = fma2(E2[r][2 * i],     uu[i].x, ax[r][par]);
                        ay[r][par] = fma2(E2[r][2 * i + 1], uu[i].y, ay[r][par]);
                    }
                }

                float sh[3];
#pragma unroll
                for (int r = 0; r < 3; r++) {
                    ull tt = add2(add2(ax[r][0], ax[r][1]),
                                  add2(ay[r][0], ay[r][1]));
                    float x, y;
                    unpack2(tt, x, y);
                    sh[r] = x + y;
                }
                // pre-multiply ex (identical on partner lane) before combine
                sh[0] *= ex0; sh[1] *= ex1; sh[2] *= ex2;

                // combine halves: after this BOTH halves hold full ex*sum
                sh[0] += __shfl_xor_sync(0xffffffffu, sh[0], 16);
                sh[1] += __shfl_xor_sync(0xffffffffu, sh[1], 16);
                sh[2] += __shfl_xor_sync(0xffffffffu, sh[2], 16);

                pr[0] = upd ? fminf(sh[0], CLAMPV) : fb0;
                pr[1] = upd ? fminf(sh[1], CLAMPV) : fb1;
                pr[2] = upd ? fminf(sh[2], CLAMPV) : fb2;

                // unconditional dual-copy store (no divergent branch)
                float* pd = &pb[w][wp][h][row0];
                pd[0] = pr[0]; pd[1] = pr[1]; pd[2] = pr[2];
            }
        }
    }

    // ---------------- tail (T % CHUNK != 0; unused for T=1024) -------------
    int t = nfull * CHUNK;
    if (t < T) {
        asm volatile("cp.async.wait_group 0;");
        const int cb = nfull & 1;
        for (int s = 0; t < T; s++, t++) {
            __syncwarp();
            const int rp = s & 1, wp = rp ^ 1;
            const ulonglong2* pu = (const ulonglong2*)(&pb[w][rp][h][jbase]);
            ulonglong2 uu[6];
#pragma unroll
            for (int i = 0; i < 6; i++) uu[i] = pu[i];
            const float* eb = &emb[w][cb][s * K + row0];
            float ex0 = __expf(eb[0]), ex1 = __expf(eb[1]), ex2 = __expf(eb[2]);
            float mk = mkb[w][cb][s];
            ull ax[3][2] = {{0,0},{0,0},{0,0}};
            ull ay[3][2] = {{0,0},{0,0},{0,0}};
#pragma unroll
            for (int i = 0; i < 6; i++) {
                const int par = i & 1;
#pragma unroll
                for (int r = 0; r < 3; r++) {
                    ax[r][par] = fma2(E2[r][2 * i],     uu[i].x, ax[r][par]);
                    ay[r][par] = fma2(E2[r][2 * i + 1], uu[i].y, ay[r][par]);
                }
            }
            float sr[3];
#pragma unroll
            for (int r = 0; r < 3; r++) {
                ull tt = add2(add2(ax[r][0], ax[r][1]), add2(ay[r][0], ay[r][1]));
                float x, y; unpack2(tt, x, y); sr[r] = x + y;
            }
            sr[0] += __shfl_xor_sync(0xffffffffu, sr[0], 16);
            sr[1] += __shfl_xor_sync(0xffffffffu, sr[1], 16);
            sr[2] += __shfl_xor_sync(0xffffffffu, sr[2], 16);
            float n0 = fminf(ex0 * sr[0], CLAMPV);
            float n1 = fminf(ex1 * sr[1], CLAMPV);
            float n2 = fminf(ex2 * sr[2], CLAMPV);
            bool upd = (mk != 0.0f);
            pr[0] = upd ? n0 : pr[0];
            pr[1] = upd ? n1 : pr[1];
            pr[2] = upd ? n2 : pr[2];
            if ((t & 7) == 7) {
                float d = __shfl_sync(0xffffffffu, pr[0], 0);
                float sc;
                asm("rcp.approx.f32 %0, %1;" : "=f"(sc) : "f"(d));
                pr[0] *= sc; pr[1] *= sc; pr[2] *= sc;
                c += __logf(d);
            }
            float* pd = &pb[w][wp][h][row0];
            pd[0] = pr[0]; pd[1] = pr[1]; pd[2] = pr[2];
        }
    }

    // ---------------- finalize: out = c + log( sum_k p_k e^{trans[STOP][k]} )
    // pr identical on both lane halves -> only lanes 0-15 contribute.
    float v = 0.0f;
    if (lane < 16) {
        const float* ts = trans + STOPID * K + row0;
        v = pr[0] * __expf(ts[0]) + pr[1] * __expf(ts[1]) + pr[2] * __expf(ts[2]);
    }
#pragma unroll
    for (int o = 16; o; o >>= 1)
        v += __shfl_xor_sync(0xffffffffu, v, o);
    if (lane == 0) out[b] = c + __logf(v);
}

extern "C" void kernel_launch(void* const* d_in, const int* in_sizes, int n_in,
                              void* d_out, int out_size)
{
    // Identify inputs by size: h_tag = largest, trans = smallest, mask = other
    int iH = 0, iT = 0;
    for (int i = 1; i < 3; i++) {
        if (in_sizes[i] > in_sizes[iH]) iH = i;
        if (in_sizes[i] < in_sizes[iT]) iT = i;
    }
    int iM = 3 - iH - iT;

    const float* h_tag = (const float*)d_in[iH];
    const float* mask  = (const float*)d_in[iM];
    const float* trans = (const float*)d_in[iT];
    float* out = (float*)d_out;

    int B = out_size;             // 512
    int T = in_sizes[iM] / B;     // 1024

    dim3 block(128);              // 4 warps, 1/SMSP, 1 sequence per warp
    dim3 grid((B + NWARP - 1) / NWARP);
    crf_fwd_kernel<<<grid, block>>>(h_tag, mask, trans, out, B, T);
}

// round 12
// speedup vs baseline: 1.0347x; 1.0347x over previous
#include <cuda_runtime.h>

#define K 48
#define STOPID 47
#define CHUNK 16
#define NWARP 4
#define CLAMPV 1e32f

typedef unsigned long long ull;

// ---------- packed f32x2 helpers (Blackwell sm_103a) ----------
__device__ __forceinline__ ull pack2(float x, float y) {
    ull r;
    asm("mov.b64 %0, {%1, %2};" : "=l"(r)
        : "r"(__float_as_uint(x)), "r"(__float_as_uint(y)));
    return r;
}
__device__ __forceinline__ void unpack2(ull v, float& x, float& y) {
    unsigned int a, b;
    asm("mov.b64 {%0, %1}, %2;" : "=r"(a), "=r"(b) : "l"(v));
    x = __uint_as_float(a);
    y = __uint_as_float(b);
}
__device__ __forceinline__ ull fma2(ull a, ull b, ull c) {
    ull d;
    asm("fma.rn.f32x2 %0, %1, %2, %3;" : "=l"(d) : "l"(a), "l"(b), "l"(c));
    return d;
}
__device__ __forceinline__ ull add2(ull a, ull b) {
    ull d;
    asm("add.rn.f32x2 %0, %1, %2;" : "=l"(d) : "l"(a), "l"(b));
    return d;
}
__device__ __forceinline__ void cp_async16(unsigned int s, const void* g) {
    asm volatile("cp.async.cg.shared.global [%0], [%1], 16;" :: "r"(s), "l"(g));
}

// One warp per sequence (512 warps, 1/SMSP — proven optimal geometry).
// PARTIAL-SUM EXCHANGE (R11): lane group h in {0,1} covers j in [24h,24h+24)
// for ALL 48 rows (lane l16 owns rows 3*l16..3*l16+2). Each group stores its
// j-half PARTIAL result vector a_h to its own smem array — no shfl combine.
// By linearity E(a0+a1) = E a0 + E a1, the consumer adds the two partials at
// the chain HEAD (12 add2, 4 cyc) instead of a 26-cyc shfl at the tail.
// Mask select per group: store = upd ? a_h : prev_h  (sum = blended p).
// State in probability space: p' = exp(emit) * (E p), E = exp(trans) in 36
// packed regs/lane. Emissions via cp.async double-buffered 16-step chunks.
// Renorm every 8th step, folded OFF-chain: scale ex and fallback by
// rcp(p0_in) where p0_in = a0[0]+a1[0] (two off-chain broadcast LDS).
__global__ __launch_bounds__(128, 1) void crf_fwd_kernel(
    const float* __restrict__ h_tag,   // [B, T, K]
    const float* __restrict__ mask,    // [B, T]
    const float* __restrict__ trans,   // [K, K]
    float* __restrict__ out,           // [B]
    int B, int T)
{
    __shared__ __align__(16) float emb[NWARP][2][CHUNK * K];  // emit chunks
    __shared__ __align__(16) float mkb[NWARP][2][CHUNK];      // mask chunks
    __shared__ __align__(16) float pb [NWARP][2][2][K];       // [buf][group][K]

    const int w    = threadIdx.x >> 5;
    const int lane = threadIdx.x & 31;
    const int b    = blockIdx.x * NWARP + w;
    if (b >= B) return;

    const int l16   = lane & 15;
    const int h     = lane >> 4;
    const int row0  = 3 * l16;
    const int jbase = 24 * h;

    // E2[r][m] = ( exp(trans[row0+r][jbase+2m]), exp(trans[row0+r][jbase+2m+1]) )
    ull E2[3][12];
#pragma unroll
    for (int r = 0; r < 3; r++) {
        const float* tr = trans + (row0 + r) * K + jbase;
#pragma unroll
        for (int m = 0; m < 12; m++)
            E2[r][m] = pack2(__expf(tr[2 * m]), __expf(tr[2 * m + 1]));
    }

    const float* hb = h_tag + (size_t)b * T * K;
    const float* mb = mask + (size_t)b * T;

    // init: score = NEG except STOP=0 -> c=-1e4, p=1 normal, p_STOP clamped to
    // 1e32 (feeds only the PAD track, ~e^4000 below answer; validated R3-R10).
    // Partials: group 0 carries the full init value, group 1 carries zero.
    float pr[3], c = -1.0e4f;
#pragma unroll
    for (int r = 0; r < 3; r++) {
        float full = (row0 + r == STOPID) ? CLAMPV : 1.0f;
        pr[r] = (h == 0) ? full : 0.0f;
        pb[w][0][h][row0 + r] = pr[r];
    }

    const int nc    = (T + CHUNK - 1) / CHUNK;
    const int nfull = T / CHUNK;

    auto prefetch = [&](int ch) {
        const int t0n = ch * CHUNK;
        const int nb  = ch & 1;
        const size_t base = (size_t)t0n * K;
        unsigned int se = (unsigned int)__cvta_generic_to_shared(&emb[w][nb][0]);
#pragma unroll
        for (int i = 0; i < 6; i++) {     // CHUNK*K*4 = 3072B = 192 x 16B
            int seg = lane + 32 * i;
            if (base + (size_t)(seg + 1) * 4 <= (size_t)T * K)
                cp_async16(se + seg * 16, hb + base + seg * 4);
        }
        unsigned int sm = (unsigned int)__cvta_generic_to_shared(&mkb[w][nb][0]);
        if (lane < 4 && t0n + (lane + 1) * 4 <= T)
            cp_async16(sm + lane * 16, mb + t0n + lane * 4);
        asm volatile("cp.async.commit_group;");
    };

    prefetch(0);

    // ---------------- main: full 16-step chunks, 8-step unrolled bodies ----
    for (int ch = 0; ch < nfull; ch++) {
        const int cb = ch & 1;
        if (ch + 1 < nc) {
            prefetch(ch + 1);
            asm volatile("cp.async.wait_group 1;");
        } else {
            asm volatile("cp.async.wait_group 0;");
        }

        for (int hf = 0; hf < 2; hf++) {
            const float* ebh = &emb[w][cb][hf * 8 * K + row0];
            const float* mkh = &mkb[w][cb][hf * 8];
#pragma unroll
            for (int s8 = 0; s8 < 8; s8++) {
                const int  rp = s8 & 1;        // read parity (hf*8 is even)
                const int  wp = rp ^ 1;
                const bool RN = (s8 == 7);     // compile-time renorm predicate

                __syncwarp();

                // chain head: both partial vectors for this lane's j-half
                const ulonglong2* pL =
                    (const ulonglong2*)(&pb[w][rp][0][jbase]);
                const ulonglong2* pR =
                    (const ulonglong2*)(&pb[w][rp][1][jbase]);
                ulonglong2 L0 = pL[0], L1 = pL[1], L2 = pL[2];
                ulonglong2 L3 = pL[3], L4 = pL[4], L5 = pL[5];
                ulonglong2 R0 = pR[0], R1 = pR[1], R2 = pR[2];
                ulonglong2 R3 = pR[3], R4 = pR[4], R5 = pR[5];

                // ---- off-chain work (runs under the fma burst) ----
                const float* eb = ebh + s8 * K;
                float ex0 = __expf(eb[0]);
                float ex1 = __expf(eb[1]);
                float ex2 = __expf(eb[2]);
                float mk  = mkh[s8];
                bool  upd = (mk != 0.0f);

                float fb0 = pr[0], fb1 = pr[1], fb2 = pr[2]; // mask fallback
                if (RN) {
                    float p0in = pb[w][rp][0][0] + pb[w][rp][1][0];
                    float rv;
                    asm("rcp.approx.f32 %0, %1;" : "=f"(rv) : "f"(p0in));
                    ex0 *= rv; ex1 *= rv; ex2 *= rv;   // renorm folded off-chain
                    fb0 *= rv; fb1 *= rv; fb2 *= rv;
                    c += __logf(p0in);
                }

                // combine partials at chain head (4-cyc dep, not 26-cyc shfl)
                ull q[12];
                q[0]  = add2(L0.x, R0.x);  q[1]  = add2(L0.y, R0.y);
                q[2]  = add2(L1.x, R1.x);  q[3]  = add2(L1.y, R1.y);
                q[4]  = add2(L2.x, R2.x);  q[5]  = add2(L2.y, R2.y);
                q[6]  = add2(L3.x, R3.x);  q[7]  = add2(L3.y, R3.y);
                q[8]  = add2(L4.x, R4.x);  q[9]  = add2(L4.y, R4.y);
                q[10] = add2(L5.x, R5.x);  q[11] = add2(L5.y, R5.y);

                // ---- 36 fma2, 12 accumulators (3-deep chains) ----
                ull ac[3][4] = {{0,0,0,0},{0,0,0,0},{0,0,0,0}};
#pragma unroll
                for (int m = 0; m < 12; m++) {
                    const int par = m & 3;
#pragma unroll
                    for (int r = 0; r < 3; r++)
                        ac[r][par] = fma2(E2[r][m], q[m], ac[r][par]);
                }

#pragma unroll
                for (int r = 0; r < 3; r++) {
                    ull tt = add2(add2(ac[r][0], ac[r][1]),
                                  add2(ac[r][2], ac[r][3]));
                    float x, y;
                    unpack2(tt, x, y);
                    float s = x + y;
                    float e = (r == 0) ? ex0 : (r == 1) ? ex1 : ex2;
                    float f = (r == 0) ? fb0 : (r == 1) ? fb1 : fb2;
                    s = fminf(e * s, CLAMPV);
                    pr[r] = upd ? s : f;
                }

                // store THIS group's partial (no combine, no divergence)
                float* pd = &pb[w][wp][h][row0];
                pd[0] = pr[0]; pd[1] = pr[1]; pd[2] = pr[2];
            }
        }
    }

    // ---------------- tail (T % CHUNK != 0; unused for T=1024) -------------
    int t = nfull * CHUNK;
    if (t < T) {
        asm volatile("cp.async.wait_group 0;");
        const int cb = nfull & 1;
        for (int s = 0; t < T; s++, t++) {
            __syncwarp();
            const int rp = t & 1, wp = rp ^ 1;
            const bool RN = ((t & 7) == 7);
            const ulonglong2* pL = (const ulonglong2*)(&pb[w][rp][0][jbase]);
            const ulonglong2* pR = (const ulonglong2*)(&pb[w][rp][1][jbase]);
            ull q[12];
#pragma unroll
            for (int i = 0; i < 6; i++) {
                ulonglong2 L = pL[i], R = pR[i];
                q[2 * i]     = add2(L.x, R.x);
                q[2 * i + 1] = add2(L.y, R.y);
            }
            const float* eb = &emb[w][cb][s * K + row0];
            float ex0 = __expf(eb[0]), ex1 = __expf(eb[1]), ex2 = __expf(eb[2]);
            float mk = mkb[w][cb][s];
            bool upd = (mk != 0.0f);
            float fb0 = pr[0], fb1 = pr[1], fb2 = pr[2];
            if (RN) {
                float p0in = pb[w][rp][0][0] + pb[w][rp][1][0];
                float rv;
                asm("rcp.approx.f32 %0, %1;" : "=f"(rv) : "f"(p0in));
                ex0 *= rv; ex1 *= rv; ex2 *= rv;
                fb0 *= rv; fb1 *= rv; fb2 *= rv;
                c += __logf(p0in);
            }
            ull ac[3][4] = {{0,0,0,0},{0,0,0,0},{0,0,0,0}};
#pragma unroll
            for (int m = 0; m < 12; m++) {
                const int par = m & 3;
#pragma unroll
                for (int r = 0; r < 3; r++)
                    ac[r][par] = fma2(E2[r][m], q[m], ac[r][par]);
            }
#pragma unroll
            for (int r = 0; r < 3; r++) {
                ull tt = add2(add2(ac[r][0], ac[r][1]), add2(ac[r][2], ac[r][3]));
                float x, y;
                unpack2(tt, x, y);
                float sv = x + y;
                float e = (r == 0) ? ex0 : (r == 1) ? ex1 : ex2;
                float f = (r == 0) ? fb0 : (r == 1) ? fb1 : fb2;
                sv = fminf(e * sv, CLAMPV);
                pr[r] = upd ? sv : f;
            }
            float* pd = &pb[w][wp][h][row0];
            pd[0] = pr[0]; pd[1] = pr[1]; pd[2] = pr[2];
        }
    }

    // ---------------- finalize: out = c + log( sum_k p_k e^{trans[STOP][k]} )
    // pr holds per-group PARTIALS: every row appears once in each group, so
    // the full 32-lane reduction sums a0+a1 per row automatically.
    float v;
    {
        const float* ts = trans + STOPID * K + row0;
        v = pr[0] * __expf(ts[0]) + pr[1] * __expf(ts[1]) + pr[2] * __expf(ts[2]);
    }
#pragma unroll
    for (int o = 16; o; o >>= 1)
        v += __shfl_xor_sync(0xffffffffu, v, o);
    if (lane == 0) out[b] = c + __logf(v);
}

extern "C" void kernel_launch(void* const* d_in, const int* in_sizes, int n_in,
                              void* d_out, int out_size)
{
    // Identify inputs by size: h_tag = largest, trans = smallest, mask = other
    int iH = 0, iT = 0;
    for (int i = 1; i < 3; i++) {
        if (in_sizes[i] > in_sizes[iH]) iH = i;
        if (in_sizes[i] < in_sizes[iT]) iT = i;
    }
    int iM = 3 - iH - iT;

    const float* h_tag = (const float*)d_in[iH];
    const float* mask  = (const float*)d_in[iM];
    const float* trans = (const float*)d_in[iT];
    float* out = (float*)d_out;

    int B = out_size;             // 512
    int T = in_sizes[iM] / B;     // 1024

    dim3 block(128);              // 4 warps, 1/SMSP, 1 sequence per warp
    dim3 grid((B + NWARP - 1) / NWARP);
    crf_fwd_kernel<<<grid, block>>>(h_tag, mask, trans, out, B, T);
}